// round 15
// baseline (speedup 1.0000x reference)
#include <cuda_runtime.h>
#include <cuda_fp16.h>
#include <math.h>
#include <stdint.h>

#define N_E 16384
#define N_A 4096
#define NF  128
#define NM  25

// ---------------- scratch (device globals; no allocation allowed) ----------------
__device__ float g_y0[(size_t)N_E * NM * NF];   // final y (post gemm2+res)
__device__ float g_y1[(size_t)N_E * NM * NF];   // post-mish edge features
__device__ float g_z[(size_t)N_A * NM * NF];    // per-ATOM W1 transform
__device__ float g_rad[(size_t)N_E * NF];
__device__ float g_shg[(size_t)N_E * 9];
__device__ float g_v[(size_t)N_E * 3 * NF];
__device__ float g_C[23 * 729];                 // real CG tables [p][a][b][c] strides 81,9,1
// precomputed B register fragments (fp16): [13 mats][2 wc64][8 kstep][4 bt][32 lane]
__device__ uint4 g_Bf[13 * 2 * 8 * 4 * 32];

__constant__ int dPL1[23]  = {0,0,0,0,0, 1,1,1,1,1,1,1,1, 2,2,2,2,2,2,2,2,2,2};
__constant__ int dPL2[23]  = {0,1,2,3,4, 0,1,1,2,2,3,3,4, 0,1,1,2,2,2,3,3,4,4};
__constant__ int dPL3[23]  = {0,1,2,3,4, 1,0,2,1,3,2,4,3, 2,1,3,0,2,4,1,3,2,4};
__constant__ int dMOFF[24] = {0,1,10,35,84,165,168,171,186,201,236,271,334,
                              397,402,411,432,437,462,507,528,577,622,703};

// ---------------- CG table computation (double, matches reference) ----------------
__device__ double factd(int n) { double r = 1.0; for (int i = 2; i <= n; ++i) r *= (double)i; return r; }

__device__ double cgc(int l1, int l2, int l3, int m1, int m2, int m3) {
    if (m1 + m2 != m3) return 0.0;
    if (l3 < abs(l1 - l2) || l3 > l1 + l2) return 0.0;
    double pre = sqrt((double)(2 * l3 + 1) * factd(l3 + l1 - l2) * factd(l3 - l1 + l2) *
                      factd(l1 + l2 - l3) / factd(l1 + l2 + l3 + 1));
    pre *= sqrt(factd(l3 + m3) * factd(l3 - m3) * factd(l1 - m1) * factd(l1 + m1) *
                factd(l2 - m2) * factd(l2 + m2));
    double s = 0.0;
    for (int k = 0; k <= l1 + l2 - l3; ++k) {
        int a0 = k, a1 = l1 + l2 - l3 - k, a2 = l1 - m1 - k, a3 = l2 + m2 - k;
        int a4 = l3 - l2 + m1 + k, a5 = l3 - l1 - m2 + k;
        if (a0 < 0 || a1 < 0 || a2 < 0 || a3 < 0 || a4 < 0 || a5 < 0) continue;
        double d = factd(a0) * factd(a1) * factd(a2) * factd(a3) * factd(a4) * factd(a5);
        s += ((k & 1) ? -1.0 : 1.0) / d;
    }
    return pre * s;
}

__device__ void u_elem(int l, int a, int A, double& re, double& im) {
    re = 0.0; im = 0.0;
    const double is2 = 0.70710678118654752440;
    int mA = A - l, ma = a - l;
    if (mA == 0) { if (ma == 0) re = 1.0; return; }
    int m = mA > 0 ? mA : -mA;
    double sgn = (m & 1) ? -1.0 : 1.0;
    if (mA > 0) {
        if (ma == m)       re = sgn * is2;
        else if (ma == -m) re = is2;
    } else {
        if (ma == m)       im = sgn * is2;
        else if (ma == -m) im = -is2;
    }
}

__global__ void cg_init_kernel() {
    int p = blockIdx.x;
    int l1 = dPL1[p], l2 = dPL2[p], l3 = dPL3[p];
    int n1 = 2 * l1 + 1, n2 = 2 * l2 + 1, n3 = 2 * l3 + 1;
    int total = n1 * n2 * n3;
    for (int idx = threadIdx.x; idx < total; idx += blockDim.x) {
        int A  = idx / (n2 * n3);
        int rm = idx % (n2 * n3);
        int B  = rm / n3;
        int Cc = rm % n3;
        double acc = 0.0;
        for (int a = 0; a < n1; ++a) {
            double u1r, u1i; u_elem(l1, a, A, u1r, u1i);
            if (u1r == 0.0 && u1i == 0.0) continue;
            int m1 = a - l1;
            for (int b = 0; b < n2; ++b) {
                double u2r, u2i; u_elem(l2, b, B, u2r, u2i);
                if (u2r == 0.0 && u2i == 0.0) continue;
                int m2 = b - l2;
                int m3 = m1 + m2;
                if (m3 < -l3 || m3 > l3) continue;
                double cg = cgc(l1, l2, l3, m1, m2, m3);
                if (cg == 0.0) continue;
                int c = l3 + m3;
                double u3r, u3i; u_elem(l3, c, Cc, u3r, u3i);
                double pr = u1r * u2r - u1i * u2i;
                double pi = u1r * u2i + u1i * u2r;
                acc += cg * (pr * u3r + pi * u3i);
            }
        }
        g_C[p * 729 + A * 81 + B * 9 + Cc] = (float)acc;
    }
}

// ================= mma.sync helpers =================
__device__ __forceinline__ uint32_t smem_u32(const void* p) {
    uint32_t a;
    asm("{ .reg .u64 t; cvta.to.shared.u64 t, %1; cvt.u32.u64 %0, t; }" : "=r"(a) : "l"(p));
    return a;
}
__device__ __forceinline__ void ldm4(uint32_t addr, uint32_t& a0, uint32_t& a1,
                                     uint32_t& a2, uint32_t& a3) {
    asm volatile("ldmatrix.sync.aligned.m8n8.x4.shared.b16 {%0,%1,%2,%3}, [%4];"
                 : "=r"(a0), "=r"(a1), "=r"(a2), "=r"(a3) : "r"(addr));
}
__device__ __forceinline__ void mma16816(float* c,
                                         uint32_t a0, uint32_t a1, uint32_t a2, uint32_t a3,
                                         uint32_t b0, uint32_t b1) {
    asm volatile("mma.sync.aligned.m16n8k16.row.col.f32.f16.f16.f32 "
                 "{%0,%1,%2,%3}, {%4,%5,%6,%7}, {%8,%9}, {%0,%1,%2,%3};"
                 : "+f"(c[0]), "+f"(c[1]), "+f"(c[2]), "+f"(c[3])
                 : "r"(a0), "r"(a1), "r"(a2), "r"(a3), "r"(b0), "r"(b1));
}

// padded row-major f16 tile: 64 rows x 128 cols, row stride 272 bytes (136 halves)
#define ROWB 272
#define TILE_ROWS 64
#define TILE_B (TILE_ROWS * ROWB)       // 17408 bytes per tile
#define TC_SMEM_BYTES (2 * TILE_B)      // A_hi, A_lo = 34816
#define WF_TILE_B (128 * ROWB)
#define WF_SMEM_BYTES WF_TILE_B

// ---------------- precompute B fragments (per weight matrix, fp16) ----------------
__global__ __launch_bounds__(256) void wfrag_init(const float* __restrict__ W1,
                                                  const float* __restrict__ W2,
                                                  const float* __restrict__ W3) {
    extern __shared__ char smem[];
    char* sH = smem;
    const int mat = blockIdx.x;
    const float* __restrict__ W = (mat < 5) ? (W1 + (size_t)mat * NF * NF)
                               : (mat < 10) ? (W2 + (size_t)(mat - 5) * NF * NF)
                                            : (W3 + (size_t)(mat - 10) * NF * NF);
    const int tid = threadIdx.x;

#pragma unroll
    for (int t = 0; t < 16; ++t) {
        int pos = t * 256 + tid;                // 4096 float4 slots
        int k = pos >> 5, n0 = (pos & 31) * 4;
        float4 w = *reinterpret_cast<const float4*>(W + (size_t)k * NF + n0);
        float wv[4] = {w.x, w.y, w.z, w.w};
#pragma unroll
        for (int q = 0; q < 4; ++q) {
            __half h = __float2half_rn(wv[q]);
            uint32_t off = (uint32_t)(n0 + q) * ROWB + (uint32_t)k * 2;
            *reinterpret_cast<unsigned short*>(sH + off) = reinterpret_cast<unsigned short&>(h);
        }
    }
    __syncthreads();

    if (tid < 64) {
        const int wc = tid >> 5, lane = tid & 31;
        const int b_n = ((lane >> 4) & 1) * 8 + (lane & 7);
        const int b_k = ((lane >> 3) & 1) * 8;
        const uint32_t baseH = smem_u32(sH);
        for (int kk = 0; kk < 8; ++kk) {
            for (int bt = 0; bt < 4; ++bt) {
                uint32_t boff = (uint32_t)(wc * 64 + bt * 16 + b_n) * ROWB +
                                (uint32_t)(kk * 16 + b_k) * 2;
                uint4 h;
                ldm4(baseH + boff, h.x, h.y, h.z, h.w);
                int idx = (((mat * 2 + wc) * 8 + kk) * 4 + bt) * 32 + lane;
                g_Bf[idx] = h;
            }
        }
    }
}

// ================= shared GEMM core: 64x128 CTA tile, 256 threads, 2 CTAs/SM =================
struct GemmIO {
    const float* X;
    size_t x_row_stride;
    float* Y;
    size_t y_row_stride;
    const float* bias;
    bool residual;
    const float* res;
    int mat;
};

__device__ __forceinline__ void gemm_core(const GemmIO io, int e0) {
    extern __shared__ char smem[];
    char* sA_hi = smem;
    char* sA_lo = smem + TILE_B;

    const int tid = threadIdx.x;
    const int wid = tid >> 5;
    const int lid = tid & 31;

    // ---- stage X (64 rows): 8 floats per thread-iter, one STS.128 per buffer ----
#pragma unroll
    for (int t = 0; t < 4; ++t) {
        int pos = t * 256 + tid;                // 1024 float8 slots
        int r = pos >> 4, k0 = (pos & 15) * 8;
        const float* src = io.X + (size_t)(e0 + r) * io.x_row_stride + k0;
        float4 x0 = *reinterpret_cast<const float4*>(src);
        float4 x1 = *reinterpret_cast<const float4*>(src + 4);
        __half2 h0 = __floats2half2_rn(x0.x, x0.y);
        __half2 h1 = __floats2half2_rn(x0.z, x0.w);
        __half2 h2 = __floats2half2_rn(x1.x, x1.y);
        __half2 h3 = __floats2half2_rn(x1.z, x1.w);
        __half2 l0 = __floats2half2_rn(x0.x - __low2float(h0), x0.y - __high2float(h0));
        __half2 l1 = __floats2half2_rn(x0.z - __low2float(h1), x0.w - __high2float(h1));
        __half2 l2 = __floats2half2_rn(x1.x - __low2float(h2), x1.y - __high2float(h2));
        __half2 l3 = __floats2half2_rn(x1.z - __low2float(h3), x1.w - __high2float(h3));
        uint4 hv = make_uint4(reinterpret_cast<uint32_t&>(h0), reinterpret_cast<uint32_t&>(h1),
                              reinterpret_cast<uint32_t&>(h2), reinterpret_cast<uint32_t&>(h3));
        uint4 lv = make_uint4(reinterpret_cast<uint32_t&>(l0), reinterpret_cast<uint32_t&>(l1),
                              reinterpret_cast<uint32_t&>(l2), reinterpret_cast<uint32_t&>(l3));
        uint32_t off = (uint32_t)r * ROWB + (uint32_t)k0 * 2;
        *reinterpret_cast<uint4*>(sA_hi + off) = hv;
        *reinterpret_cast<uint4*>(sA_lo + off) = lv;
    }
    __syncthreads();

    // ---- mainloop: 8 warps in 2 row-groups x 4 col-groups; warp tile 32x32 ----
    const int wr = wid >> 2;            // 0..1
    const int wc = wid & 3;             // 0..3
    const int r0 = wr * 32;

    const uint32_t aBaseHi = smem_u32(sA_hi);
    const uint32_t aBaseLo = smem_u32(sA_lo);
    const int a_r = lid & 15;
    const int a_k = (lid >> 4) * 8;

    const int wc64 = wc >> 1;
    const int btb  = (wc & 1) * 2;
    const uint4* __restrict__ Bf = g_Bf + ((size_t)(io.mat * 2 + wc64) * 8) * 128 + btb * 32 + lid;

    float acc[8][4];
#pragma unroll
    for (int t = 0; t < 8; ++t)
#pragma unroll
        for (int q = 0; q < 4; ++q) acc[t][q] = 0.f;

    uint32_t ah[2][2][4], al[2][2][4];
    uint4 bh[2][2];

#pragma unroll
    for (int rt = 0; rt < 2; ++rt) {
        uint32_t aoff = (uint32_t)(r0 + rt * 16 + a_r) * ROWB + (uint32_t)(a_k) * 2;
        ldm4(aBaseHi + aoff, ah[0][rt][0], ah[0][rt][1], ah[0][rt][2], ah[0][rt][3]);
        ldm4(aBaseLo + aoff, al[0][rt][0], al[0][rt][1], al[0][rt][2], al[0][rt][3]);
    }
#pragma unroll
    for (int bt = 0; bt < 2; ++bt) bh[0][bt] = Bf[bt * 32];

#pragma unroll
    for (int kk = 0; kk < 8; ++kk) {
        const int cur = kk & 1;
        const int nxt = cur ^ 1;
        if (kk < 7) {
#pragma unroll
            for (int bt = 0; bt < 2; ++bt) bh[nxt][bt] = Bf[(kk + 1) * 128 + bt * 32];
#pragma unroll
            for (int rt = 0; rt < 2; ++rt) {
                uint32_t aoff = (uint32_t)(r0 + rt * 16 + a_r) * ROWB +
                                (uint32_t)((kk + 1) * 16 + a_k) * 2;
                ldm4(aBaseHi + aoff, ah[nxt][rt][0], ah[nxt][rt][1], ah[nxt][rt][2], ah[nxt][rt][3]);
                ldm4(aBaseLo + aoff, al[nxt][rt][0], al[nxt][rt][1], al[nxt][rt][2], al[nxt][rt][3]);
            }
        }
#pragma unroll
        for (int bt = 0; bt < 2; ++bt) {
#pragma unroll
            for (int rt = 0; rt < 2; ++rt) {
                float* c0p = acc[rt * 4 + bt * 2];
                float* c1p = acc[rt * 4 + bt * 2 + 1];
                mma16816(c0p, ah[cur][rt][0], ah[cur][rt][1], ah[cur][rt][2], ah[cur][rt][3],
                         bh[cur][bt].x, bh[cur][bt].y);
                mma16816(c1p, ah[cur][rt][0], ah[cur][rt][1], ah[cur][rt][2], ah[cur][rt][3],
                         bh[cur][bt].z, bh[cur][bt].w);
                mma16816(c0p, al[cur][rt][0], al[cur][rt][1], al[cur][rt][2], al[cur][rt][3],
                         bh[cur][bt].x, bh[cur][bt].y);
                mma16816(c1p, al[cur][rt][0], al[cur][rt][1], al[cur][rt][2], al[cur][rt][3],
                         bh[cur][bt].z, bh[cur][bt].w);
            }
        }
    }

    // ---- direct fragment epilogue (no smem round-trip) ----
    const int c0w = wc * 32;
    const int fr = lid >> 2;
    const int fc = (lid & 3) * 2;
#pragma unroll
    for (int rt = 0; rt < 2; ++rt) {
#pragma unroll
        for (int nt = 0; nt < 4; ++nt) {
            float* a = acc[rt * 4 + nt];
            int rr = r0 + rt * 16 + fr;
            int cc = c0w + nt * 8 + fc;
            float2 v0 = make_float2(a[0], a[1]);
            float2 v1 = make_float2(a[2], a[3]);
            if (io.bias) {
                float bx = io.bias[cc], by = io.bias[cc + 1];
                v0.x += bx; v0.y += by;
                v1.x += bx; v1.y += by;
            }
            size_t o0 = (size_t)(e0 + rr) * io.y_row_stride + cc;
            size_t o1 = (size_t)(e0 + rr + 8) * io.y_row_stride + cc;
            if (io.residual) {
                float2 q0 = *reinterpret_cast<const float2*>(io.res + o0);
                float2 q1 = *reinterpret_cast<const float2*>(io.res + o1);
                v0.x += q0.x; v0.y += q0.y;
                v1.x += q1.x; v1.y += q1.y;
            }
            *reinterpret_cast<float2*>(io.Y + o0) = v0;
            *reinterpret_cast<float2*>(io.Y + o1) = v1;
        }
    }
}

// atoms: X = desc, Y = g_z, no bias
__global__ __launch_bounds__(256, 2) void tc_gemm_atom(const float* __restrict__ desc) {
    const int m = blockIdx.y;
    const int l = (m >= 16) ? 4 : (m >= 9) ? 3 : (m >= 4) ? 2 : (m >= 1) ? 1 : 0;
    GemmIO io;
    io.X = desc + (size_t)m * NF;  io.x_row_stride = NM * NF;
    io.Y = g_z + (size_t)m * NF;   io.y_row_stride = NM * NF;
    io.bias = nullptr; io.residual = false; io.res = nullptr;
    io.mat = l;
    gemm_core(io, blockIdx.x * TILE_ROWS);
}

// merged edge GEMM: m in [0,25) = W2 (+residual, b2 @ m==0); m in [25,28) = W3 (b3 @ m==25)
__global__ __launch_bounds__(256, 2) void tc_gemm_edge(const float* __restrict__ b2,
                                                       const float* __restrict__ b3) {
    const int m = blockIdx.y;
    GemmIO io;
    if (m < NM) {
        const int l = (m >= 16) ? 4 : (m >= 9) ? 3 : (m >= 4) ? 2 : (m >= 1) ? 1 : 0;
        io.X = g_y1 + (size_t)m * NF;  io.x_row_stride = NM * NF;
        io.Y = g_y0 + (size_t)m * NF;  io.y_row_stride = NM * NF;
        io.bias = (m == 0) ? b2 : nullptr;
        io.residual = true; io.res = g_y1 + (size_t)m * NF;
        io.mat = 5 + l;
    } else {
        const int l = m - NM;
        io.X = g_rad;                  io.x_row_stride = NF;
        io.Y = g_v + (size_t)l * NF;   io.y_row_stride = 3 * NF;
        io.bias = (l == 0) ? b3 : nullptr;
        io.residual = false; io.res = nullptr;
        io.mat = 10 + l;
    }
    gemm_core(io, blockIdx.x * TILE_ROWS);
}

// ---------------- fused gather + b1 + normalize + mish + rad/sh ----------------
__global__ __launch_bounds__(128) void norm_mish_gather(const int* __restrict__ nidx,
                                                        const float* __restrict__ b1,
                                                        const float* __restrict__ disp) {
    int e = blockIdx.x, f = threadIdx.x;

    {
        float dx = disp[3 * e], dy = disp[3 * e + 1], dz = disp[3 * e + 2];
        float r = sqrtf(dx * dx + dy * dy + dz * dz + 1e-12f);
        float x = dx / r, y = dy / r, z = dz / r;
        float uc = r / 5.0f;
        float denom = fmaxf(1.f - uc * uc, 1e-9f);
        float cut = (uc < 1.f) ? expf(1.f - 1.f / denom) : 0.f;
        float ang = 3.14159265358979323846f * r / 5.0f;
        g_rad[(size_t)e * NF + f] = cosf((float)f * ang) * cut;
        if (f < 9) {
            const float s3 = 1.7320508075688772f;
            float shv;
            switch (f) {
                case 0: shv = 1.f; break;
                case 1: shv = y; break;
                case 2: shv = z; break;
                case 3: shv = x; break;
                case 4: shv = s3 * x * y; break;
                case 5: shv = s3 * y * z; break;
                case 6: shv = 0.5f * (3.f * z * z - 1.f); break;
                case 7: shv = s3 * x * z; break;
                default: shv = 0.5f * s3 * (x * x - y * y); break;
            }
            g_shg[(size_t)e * 9 + f] = shv;
        }
    }

    int i = nidx[2 * e], j = nidx[2 * e + 1];
    const float* __restrict__ Zi = g_z + (size_t)i * (NM * NF) + f;
    const float* __restrict__ Zj = g_z + (size_t)j * (NM * NF) + f;
    float v[NM];
    float n2 = 0.f;
    float bf = b1[f];
#pragma unroll
    for (int m = 0; m < NM; ++m) {
        float val = Zi[(size_t)m * NF] + Zj[(size_t)m * NF];
        if (m == 0) val += bf;
        v[m] = val;
        n2 += val * val;
    }
    float sc = rsqrtf(n2 + 1e-6f);
    float s = v[0] * sc;
    float sp = fmaxf(s, 0.f) + log1pf(expf(-fabsf(s)));
    float t = tanhf(sp);
    float sig = 1.f / (1.f + expf(-s));
    float dm = t + s * (1.f - t * t) * sig;
    size_t base = (size_t)e * (NM * NF) + f;
    g_y1[base] = s * t;
#pragma unroll
    for (int m = 1; m < NM; ++m) g_y1[base + (size_t)m * NF] = v[m] * sc * dm;
}

// ---------------- tensor product (scalar) ----------------
template <int P, int L1, int L2, int L3, int MO>
__device__ __forceinline__ void tp_path(const float* __restrict__ wtp, int f,
                                        const float* __restrict__ Ms,
                                        const float (&vv)[3], const float (&yreg)[25],
                                        float (&acc)[25]) {
    float scale = wtp[P * NF + f] * vv[L1];
#pragma unroll
    for (int c = 0; c < 2 * L3 + 1; ++c) {
        float s = 0.f;
#pragma unroll
        for (int b = 0; b < 2 * L2 + 1; ++b)
            s += Ms[MO + b * (2 * L3 + 1) + c] * yreg[L2 * L2 + b];
        acc[L3 * L3 + c] += scale * s;
    }
}

__global__ __launch_bounds__(128) void tp_kernel(const float* __restrict__ wtp,
                                                 float* __restrict__ Out) {
    int e = blockIdx.x, f = threadIdx.x;
    __shared__ float Ms[703];
    __shared__ float shs[9];
    if (f < 9) shs[f] = g_shg[(size_t)e * 9 + f];
    __syncthreads();

    for (int idx = f; idx < 703; idx += 128) {
        int p = 0;
        while (dMOFF[p + 1] <= idx) ++p;
        int l1 = dPL1[p], l3 = dPL3[p];
        int local = idx - dMOFF[p];
        int n3 = 2 * l3 + 1;
        int b = local / n3, c = local - b * n3;
        const float* Cp = g_C + p * 729 + b * 9 + c;
        float s = 0.f;
        for (int a = 0; a <= 2 * l1; ++a) s += Cp[a * 81] * shs[l1 * l1 + a];
        Ms[idx] = s;
    }
    __syncthreads();

    float yreg[25];
    size_t base = (size_t)e * (NM * NF) + f;
#pragma unroll
    for (int m = 0; m < NM; ++m) yreg[m] = g_y0[base + (size_t)m * NF];
    float vv[3];
#pragma unroll
    for (int l = 0; l < 3; ++l) vv[l] = g_v[((size_t)e * 3 + l) * NF + f];
    float acc[25];
#pragma unroll
    for (int m = 0; m < NM; ++m) acc[m] = 0.f;

    tp_path<0, 0, 0, 0, 0>(wtp, f, Ms, vv, yreg, acc);
    tp_path<1, 0, 1, 1, 1>(wtp, f, Ms, vv, yreg, acc);
    tp_path<2, 0, 2, 2, 10>(wtp, f, Ms, vv, yreg, acc);
    tp_path<3, 0, 3, 3, 35>(wtp, f, Ms, vv, yreg, acc);
    tp_path<4, 0, 4, 4, 84>(wtp, f, Ms, vv, yreg, acc);
    tp_path<5, 1, 0, 1, 165>(wtp, f, Ms, vv, yreg, acc);
    tp_path<6, 1, 1, 0, 168>(wtp, f, Ms, vv, yreg, acc);
    tp_path<7, 1, 1, 2, 171>(wtp, f, Ms, vv, yreg, acc);
    tp_path<8, 1, 2, 1, 186>(wtp, f, Ms, vv, yreg, acc);
    tp_path<9, 1, 2, 3, 201>(wtp, f, Ms, vv, yreg, acc);
    tp_path<10, 1, 3, 2, 236>(wtp, f, Ms, vv, yreg, acc);
    tp_path<11, 1, 3, 4, 271>(wtp, f, Ms, vv, yreg, acc);
    tp_path<12, 1, 4, 3, 334>(wtp, f, Ms, vv, yreg, acc);
    tp_path<13, 2, 0, 2, 397>(wtp, f, Ms, vv, yreg, acc);
    tp_path<14, 2, 1, 1, 402>(wtp, f, Ms, vv, yreg, acc);
    tp_path<15, 2, 1, 3, 411>(wtp, f, Ms, vv, yreg, acc);
    tp_path<16, 2, 2, 0, 432>(wtp, f, Ms, vv, yreg, acc);
    tp_path<17, 2, 2, 2, 437>(wtp, f, Ms, vv, yreg, acc);
    tp_path<18, 2, 2, 4, 462>(wtp, f, Ms, vv, yreg, acc);
    tp_path<19, 2, 3, 1, 507>(wtp, f, Ms, vv, yreg, acc);
    tp_path<20, 2, 3, 3, 528>(wtp, f, Ms, vv, yreg, acc);
    tp_path<21, 2, 4, 2, 577>(wtp, f, Ms, vv, yreg, acc);
    tp_path<22, 2, 4, 4, 622>(wtp, f, Ms, vv, yreg, acc);

#pragma unroll
    for (int m = 0; m < NM; ++m) Out[base + (size_t)m * NF] = acc[m];
}

// ---------------- launch ----------------
extern "C" void kernel_launch(void* const* d_in, const int* in_sizes, int n_in,
                              void* d_out, int out_size) {
    const float* desc = (const float*)d_in[0];
    const int*   nidx = (const int*)d_in[1];
    const float* disp = (const float*)d_in[2];
    const float* W1   = (const float*)d_in[3];
    const float* b1   = (const float*)d_in[4];
    const float* W2   = (const float*)d_in[5];
    const float* b2   = (const float*)d_in[6];
    const float* W3   = (const float*)d_in[7];
    const float* b3   = (const float*)d_in[8];
    const float* wtp  = (const float*)d_in[9];
    float* out = (float*)d_out;
    (void)in_sizes; (void)n_in; (void)out_size;

    static int attr_set = 0;
    if (!attr_set) {
        cudaFuncSetAttribute(tc_gemm_atom, cudaFuncAttributeMaxDynamicSharedMemorySize, TC_SMEM_BYTES);
        cudaFuncSetAttribute(tc_gemm_edge, cudaFuncAttributeMaxDynamicSharedMemorySize, TC_SMEM_BYTES);
        cudaFuncSetAttribute(wfrag_init, cudaFuncAttributeMaxDynamicSharedMemorySize, WF_SMEM_BYTES);
        attr_set = 1;
    }

    cg_init_kernel<<<23, 128>>>();
    wfrag_init<<<13, 256, WF_SMEM_BYTES>>>(W1, W2, W3);
    tc_gemm_atom<<<dim3(N_A / TILE_ROWS, NM), 256, TC_SMEM_BYTES>>>(desc);
    norm_mish_gather<<<N_E, 128>>>(nidx, b1, disp);
    tc_gemm_edge<<<dim3(N_E / TILE_ROWS, NM + 3), 256, TC_SMEM_BYTES>>>(b2, b3);
    tp_kernel<<<N_E, 128>>>(wtp, out);
}

// round 16
// speedup vs baseline: 1.3201x; 1.3201x over previous
#include <cuda_runtime.h>
#include <cuda_fp16.h>
#include <math.h>
#include <stdint.h>

#define N_E 16384
#define N_A 4096
#define NF  128
#define NM  25

// ---------------- scratch (device globals; no allocation allowed) ----------------
__device__ float g_y0[(size_t)N_E * NM * NF];   // final y (post gemm2+res)
__device__ float g_y1[(size_t)N_E * NM * NF];   // post-mish edge features
__device__ float g_z[(size_t)N_A * NM * NF];    // per-ATOM W1 transform
__device__ float g_rad[(size_t)N_E * NF];
__device__ float g_shg[(size_t)N_E * 9];
__device__ float g_v[(size_t)N_E * 3 * NF];
__device__ float g_C[23 * 729];                 // real CG tables [p][a][b][c] strides 81,9,1
// precomputed B register fragments (fp16): [13 mats][2 wc64][8 kstep][4 bt][32 lane]
__device__ uint4 g_Bf[13 * 2 * 8 * 4 * 32];

__constant__ int dPL1[23]  = {0,0,0,0,0, 1,1,1,1,1,1,1,1, 2,2,2,2,2,2,2,2,2,2};
__constant__ int dPL2[23]  = {0,1,2,3,4, 0,1,1,2,2,3,3,4, 0,1,1,2,2,2,3,3,4,4};
__constant__ int dPL3[23]  = {0,1,2,3,4, 1,0,2,1,3,2,4,3, 2,1,3,0,2,4,1,3,2,4};
__constant__ int dMOFF[24] = {0,1,10,35,84,165,168,171,186,201,236,271,334,
                              397,402,411,432,437,462,507,528,577,622,703};

// ---------------- CG table computation (double, matches reference) ----------------
__device__ double factd(int n) { double r = 1.0; for (int i = 2; i <= n; ++i) r *= (double)i; return r; }

__device__ double cgc(int l1, int l2, int l3, int m1, int m2, int m3) {
    if (m1 + m2 != m3) return 0.0;
    if (l3 < abs(l1 - l2) || l3 > l1 + l2) return 0.0;
    double pre = sqrt((double)(2 * l3 + 1) * factd(l3 + l1 - l2) * factd(l3 - l1 + l2) *
                      factd(l1 + l2 - l3) / factd(l1 + l2 + l3 + 1));
    pre *= sqrt(factd(l3 + m3) * factd(l3 - m3) * factd(l1 - m1) * factd(l1 + m1) *
                factd(l2 - m2) * factd(l2 + m2));
    double s = 0.0;
    for (int k = 0; k <= l1 + l2 - l3; ++k) {
        int a0 = k, a1 = l1 + l2 - l3 - k, a2 = l1 - m1 - k, a3 = l2 + m2 - k;
        int a4 = l3 - l2 + m1 + k, a5 = l3 - l1 - m2 + k;
        if (a0 < 0 || a1 < 0 || a2 < 0 || a3 < 0 || a4 < 0 || a5 < 0) continue;
        double d = factd(a0) * factd(a1) * factd(a2) * factd(a3) * factd(a4) * factd(a5);
        s += ((k & 1) ? -1.0 : 1.0) / d;
    }
    return pre * s;
}

__device__ void u_elem(int l, int a, int A, double& re, double& im) {
    re = 0.0; im = 0.0;
    const double is2 = 0.70710678118654752440;
    int mA = A - l, ma = a - l;
    if (mA == 0) { if (ma == 0) re = 1.0; return; }
    int m = mA > 0 ? mA : -mA;
    double sgn = (m & 1) ? -1.0 : 1.0;
    if (mA > 0) {
        if (ma == m)       re = sgn * is2;
        else if (ma == -m) re = is2;
    } else {
        if (ma == m)       im = sgn * is2;
        else if (ma == -m) im = -is2;
    }
}

// parallelized: grid (23, 8) — 1024 threads per path cover <=729 elements
__global__ void cg_init_kernel() {
    int p = blockIdx.x;
    int l1 = dPL1[p], l2 = dPL2[p], l3 = dPL3[p];
    int n1 = 2 * l1 + 1, n2 = 2 * l2 + 1, n3 = 2 * l3 + 1;
    int total = n1 * n2 * n3;
    int start = blockIdx.y * blockDim.x + threadIdx.x;
    int stride = blockDim.x * gridDim.y;
    for (int idx = start; idx < total; idx += stride) {
        int A  = idx / (n2 * n3);
        int rm = idx % (n2 * n3);
        int B  = rm / n3;
        int Cc = rm % n3;
        double acc = 0.0;
        for (int a = 0; a < n1; ++a) {
            double u1r, u1i; u_elem(l1, a, A, u1r, u1i);
            if (u1r == 0.0 && u1i == 0.0) continue;
            int m1 = a - l1;
            for (int b = 0; b < n2; ++b) {
                double u2r, u2i; u_elem(l2, b, B, u2r, u2i);
                if (u2r == 0.0 && u2i == 0.0) continue;
                int m2 = b - l2;
                int m3 = m1 + m2;
                if (m3 < -l3 || m3 > l3) continue;
                double cg = cgc(l1, l2, l3, m1, m2, m3);
                if (cg == 0.0) continue;
                int c = l3 + m3;
                double u3r, u3i; u_elem(l3, c, Cc, u3r, u3i);
                double pr = u1r * u2r - u1i * u2i;
                double pi = u1r * u2i + u1i * u2r;
                acc += cg * (pr * u3r + pi * u3i);
            }
        }
        g_C[p * 729 + A * 81 + B * 9 + Cc] = (float)acc;
    }
}

// ================= mma.sync helpers =================
__device__ __forceinline__ uint32_t smem_u32(const void* p) {
    uint32_t a;
    asm("{ .reg .u64 t; cvta.to.shared.u64 t, %1; cvt.u32.u64 %0, t; }" : "=r"(a) : "l"(p));
    return a;
}
__device__ __forceinline__ void ldm4(uint32_t addr, uint32_t& a0, uint32_t& a1,
                                     uint32_t& a2, uint32_t& a3) {
    asm volatile("ldmatrix.sync.aligned.m8n8.x4.shared.b16 {%0,%1,%2,%3}, [%4];"
                 : "=r"(a0), "=r"(a1), "=r"(a2), "=r"(a3) : "r"(addr));
}
__device__ __forceinline__ void mma16816(float* c,
                                         uint32_t a0, uint32_t a1, uint32_t a2, uint32_t a3,
                                         uint32_t b0, uint32_t b1) {
    asm volatile("mma.sync.aligned.m16n8k16.row.col.f32.f16.f16.f32 "
                 "{%0,%1,%2,%3}, {%4,%5,%6,%7}, {%8,%9}, {%0,%1,%2,%3};"
                 : "+f"(c[0]), "+f"(c[1]), "+f"(c[2]), "+f"(c[3])
                 : "r"(a0), "r"(a1), "r"(a2), "r"(a3), "r"(b0), "r"(b1));
}

// padded row-major f16 tile: 128 rows x 128 cols, row stride 272 bytes (136 halves)
#define ROWB 272
#define TILE_B (128 * ROWB)           // 34816 bytes per tile
#define TC_SMEM_BYTES (2 * TILE_B)    // A_hi, A_lo = 69632
#define WF_SMEM_BYTES TILE_B

// ---------------- precompute B fragments (per weight matrix, fp16) ----------------
__global__ __launch_bounds__(256) void wfrag_init(const float* __restrict__ W1,
                                                  const float* __restrict__ W2,
                                                  const float* __restrict__ W3) {
    extern __shared__ char smem[];
    char* sH = smem;
    const int mat = blockIdx.x;
    const float* __restrict__ W = (mat < 5) ? (W1 + (size_t)mat * NF * NF)
                               : (mat < 10) ? (W2 + (size_t)(mat - 5) * NF * NF)
                                            : (W3 + (size_t)(mat - 10) * NF * NF);
    const int tid = threadIdx.x;

#pragma unroll
    for (int t = 0; t < 16; ++t) {
        int pos = t * 256 + tid;                // 4096 float4 slots
        int k = pos >> 5, n0 = (pos & 31) * 4;
        float4 w = *reinterpret_cast<const float4*>(W + (size_t)k * NF + n0);
        float wv[4] = {w.x, w.y, w.z, w.w};
#pragma unroll
        for (int q = 0; q < 4; ++q) {
            __half h = __float2half_rn(wv[q]);
            uint32_t off = (uint32_t)(n0 + q) * ROWB + (uint32_t)k * 2;
            *reinterpret_cast<unsigned short*>(sH + off) = reinterpret_cast<unsigned short&>(h);
        }
    }
    __syncthreads();

    if (tid < 64) {
        const int wc = tid >> 5, lane = tid & 31;
        const int b_n = ((lane >> 4) & 1) * 8 + (lane & 7);
        const int b_k = ((lane >> 3) & 1) * 8;
        const uint32_t baseH = smem_u32(sH);
        for (int kk = 0; kk < 8; ++kk) {
            for (int bt = 0; bt < 4; ++bt) {
                uint32_t boff = (uint32_t)(wc * 64 + bt * 16 + b_n) * ROWB +
                                (uint32_t)(kk * 16 + b_k) * 2;
                uint4 h;
                ldm4(baseH + boff, h.x, h.y, h.z, h.w);
                int idx = (((mat * 2 + wc) * 8 + kk) * 4 + bt) * 32 + lane;
                g_Bf[idx] = h;
            }
        }
    }
}

// ================= shared GEMM core (R12: fp16 2-product, Cs epilogue) =================
struct GemmIO {
    const float* X;
    size_t x_row_stride;
    float* Y;
    size_t y_row_stride;
    const float* bias;
    bool residual;
    const float* res;
    int mat;
};

__device__ __forceinline__ void gemm_core(const GemmIO io, int e0) {
    extern __shared__ char smem[];
    char* sA_hi = smem;
    char* sA_lo = smem + TILE_B;
    float* Cs = reinterpret_cast<float*>(smem);   // reused after sync

    const int tid = threadIdx.x;
    const int wid = tid >> 5;
    const int lid = tid & 31;

    // ---- stage X into A_hi/A_lo (fp16 split; x = xh + xl to ~2^-22) ----
#pragma unroll
    for (int t = 0; t < 8; ++t) {
        int pos = t * 512 + tid;
        int r = pos >> 5, k0 = (pos & 31) * 4;
        float4 x = *reinterpret_cast<const float4*>(io.X + (size_t)(e0 + r) * io.x_row_stride + k0);
        __half2 h01 = __floats2half2_rn(x.x, x.y);
        __half2 h23 = __floats2half2_rn(x.z, x.w);
        __half2 l01 = __floats2half2_rn(x.x - __low2float(h01), x.y - __high2float(h01));
        __half2 l23 = __floats2half2_rn(x.z - __low2float(h23), x.w - __high2float(h23));
        uint32_t off = (uint32_t)r * ROWB + (uint32_t)k0 * 2;
        *reinterpret_cast<uint32_t*>(sA_hi + off)     = reinterpret_cast<uint32_t&>(h01);
        *reinterpret_cast<uint32_t*>(sA_hi + off + 4) = reinterpret_cast<uint32_t&>(h23);
        *reinterpret_cast<uint32_t*>(sA_lo + off)     = reinterpret_cast<uint32_t&>(l01);
        *reinterpret_cast<uint32_t*>(sA_lo + off + 4) = reinterpret_cast<uint32_t&>(l23);
    }
    __syncthreads();

    // ---- pipelined mainloop: warps 4 rows x 4 cols; warp tile 32x32 ----
    const int wr = wid >> 2;
    const int wc = wid & 3;
    const int r0 = wr * 32;

    const uint32_t aBaseHi = smem_u32(sA_hi);
    const uint32_t aBaseLo = smem_u32(sA_lo);
    const int a_r = lid & 15;
    const int a_k = (lid >> 4) * 8;

    const int wc64 = wc >> 1;
    const int btb  = (wc & 1) * 2;
    const uint4* __restrict__ Bf = g_Bf + ((size_t)(io.mat * 2 + wc64) * 8) * 128 + btb * 32 + lid;

    float acc[8][4];
#pragma unroll
    for (int t = 0; t < 8; ++t)
#pragma unroll
        for (int q = 0; q < 4; ++q) acc[t][q] = 0.f;

    uint32_t ah[2][2][4], al[2][2][4];
    uint4 bh[2][2];

#pragma unroll
    for (int rt = 0; rt < 2; ++rt) {
        uint32_t aoff = (uint32_t)(r0 + rt * 16 + a_r) * ROWB + (uint32_t)(a_k) * 2;
        ldm4(aBaseHi + aoff, ah[0][rt][0], ah[0][rt][1], ah[0][rt][2], ah[0][rt][3]);
        ldm4(aBaseLo + aoff, al[0][rt][0], al[0][rt][1], al[0][rt][2], al[0][rt][3]);
    }
#pragma unroll
    for (int bt = 0; bt < 2; ++bt) bh[0][bt] = Bf[bt * 32];

#pragma unroll
    for (int kk = 0; kk < 8; ++kk) {
        const int cur = kk & 1;
        const int nxt = cur ^ 1;
        if (kk < 7) {
#pragma unroll
            for (int bt = 0; bt < 2; ++bt) bh[nxt][bt] = Bf[(kk + 1) * 128 + bt * 32];
#pragma unroll
            for (int rt = 0; rt < 2; ++rt) {
                uint32_t aoff = (uint32_t)(r0 + rt * 16 + a_r) * ROWB +
                                (uint32_t)((kk + 1) * 16 + a_k) * 2;
                ldm4(aBaseHi + aoff, ah[nxt][rt][0], ah[nxt][rt][1], ah[nxt][rt][2], ah[nxt][rt][3]);
                ldm4(aBaseLo + aoff, al[nxt][rt][0], al[nxt][rt][1], al[nxt][rt][2], al[nxt][rt][3]);
            }
        }
#pragma unroll
        for (int bt = 0; bt < 2; ++bt) {
#pragma unroll
            for (int rt = 0; rt < 2; ++rt) {
                float* c0p = acc[rt * 4 + bt * 2];
                float* c1p = acc[rt * 4 + bt * 2 + 1];
                mma16816(c0p, ah[cur][rt][0], ah[cur][rt][1], ah[cur][rt][2], ah[cur][rt][3],
                         bh[cur][bt].x, bh[cur][bt].y);
                mma16816(c1p, ah[cur][rt][0], ah[cur][rt][1], ah[cur][rt][2], ah[cur][rt][3],
                         bh[cur][bt].z, bh[cur][bt].w);
                mma16816(c0p, al[cur][rt][0], al[cur][rt][1], al[cur][rt][2], al[cur][rt][3],
                         bh[cur][bt].x, bh[cur][bt].y);
                mma16816(c1p, al[cur][rt][0], al[cur][rt][1], al[cur][rt][2], al[cur][rt][3],
                         bh[cur][bt].z, bh[cur][bt].w);
            }
        }
    }
    __syncthreads();   // done reading A; safe to reuse as Cs

    // ---- write fragments to Cs (row stride 132 floats) ----
    const int c0w = wc * 32;
#pragma unroll
    for (int rt = 0; rt < 2; ++rt) {
#pragma unroll
        for (int nt = 0; nt < 4; ++nt) {
            float* a = acc[rt * 4 + nt];
            int rr = r0 + rt * 16 + (lid >> 2);
            int cc = c0w + nt * 8 + (lid & 3) * 2;
            *reinterpret_cast<float2*>(Cs + (size_t)rr * 132 + cc)       = make_float2(a[0], a[1]);
            *reinterpret_cast<float2*>(Cs + (size_t)(rr + 8) * 132 + cc) = make_float2(a[2], a[3]);
        }
    }
    __syncthreads();

    // ---- coalesced epilogue: bias, residual, store ----
#pragma unroll
    for (int t = 0; t < 8; ++t) {
        int pos = t * 512 + tid;
        int r = pos >> 5, c4 = (pos & 31) * 4;
        float4 o = *reinterpret_cast<const float4*>(Cs + (size_t)r * 132 + c4);
        if (io.bias) {
            o.x += io.bias[c4]; o.y += io.bias[c4 + 1];
            o.z += io.bias[c4 + 2]; o.w += io.bias[c4 + 3];
        }
        size_t obase = (size_t)(e0 + r) * io.y_row_stride + c4;
        if (io.residual) {
            float4 rsd = *reinterpret_cast<const float4*>(io.res + obase);
            o.x += rsd.x; o.y += rsd.y; o.z += rsd.z; o.w += rsd.w;
        }
        *reinterpret_cast<float4*>(io.Y + obase) = o;
    }
}

// atoms: X = desc, Y = g_z, no bias
__global__ __launch_bounds__(512, 1) void tc_gemm_atom(const float* __restrict__ desc) {
    const int m = blockIdx.y;
    const int l = (m >= 16) ? 4 : (m >= 9) ? 3 : (m >= 4) ? 2 : (m >= 1) ? 1 : 0;
    GemmIO io;
    io.X = desc + (size_t)m * NF;  io.x_row_stride = NM * NF;
    io.Y = g_z + (size_t)m * NF;   io.y_row_stride = NM * NF;
    io.bias = nullptr; io.residual = false; io.res = nullptr;
    io.mat = l;
    gemm_core(io, blockIdx.x * 128);
}

// merged edge GEMM: m in [0,25) = W2 (+residual, b2 @ m==0); m in [25,28) = W3 (b3 @ m==25)
__global__ __launch_bounds__(512, 1) void tc_gemm_edge(const float* __restrict__ b2,
                                                       const float* __restrict__ b3) {
    const int m = blockIdx.y;
    GemmIO io;
    if (m < NM) {
        const int l = (m >= 16) ? 4 : (m >= 9) ? 3 : (m >= 4) ? 2 : (m >= 1) ? 1 : 0;
        io.X = g_y1 + (size_t)m * NF;  io.x_row_stride = NM * NF;
        io.Y = g_y0 + (size_t)m * NF;  io.y_row_stride = NM * NF;
        io.bias = (m == 0) ? b2 : nullptr;
        io.residual = true; io.res = g_y1 + (size_t)m * NF;
        io.mat = 5 + l;
    } else {
        const int l = m - NM;
        io.X = g_rad;                  io.x_row_stride = NF;
        io.Y = g_v + (size_t)l * NF;   io.y_row_stride = 3 * NF;
        io.bias = (l == 0) ? b3 : nullptr;
        io.residual = false; io.res = nullptr;
        io.mat = 10 + l;
    }
    gemm_core(io, blockIdx.x * 128);
}

// ---------------- fused gather + b1 + normalize + mish + rad/sh ----------------
__global__ __launch_bounds__(128) void norm_mish_gather(const int* __restrict__ nidx,
                                                        const float* __restrict__ b1,
                                                        const float* __restrict__ disp) {
    int e = blockIdx.x, f = threadIdx.x;

    {
        float dx = disp[3 * e], dy = disp[3 * e + 1], dz = disp[3 * e + 2];
        float r = sqrtf(dx * dx + dy * dy + dz * dz + 1e-12f);
        float x = dx / r, y = dy / r, z = dz / r;
        float uc = r / 5.0f;
        float denom = fmaxf(1.f - uc * uc, 1e-9f);
        float cut = (uc < 1.f) ? expf(1.f - 1.f / denom) : 0.f;
        float ang = 3.14159265358979323846f * r / 5.0f;
        g_rad[(size_t)e * NF + f] = cosf((float)f * ang) * cut;
        if (f < 9) {
            const float s3 = 1.7320508075688772f;
            float shv;
            switch (f) {
                case 0: shv = 1.f; break;
                case 1: shv = y; break;
                case 2: shv = z; break;
                case 3: shv = x; break;
                case 4: shv = s3 * x * y; break;
                case 5: shv = s3 * y * z; break;
                case 6: shv = 0.5f * (3.f * z * z - 1.f); break;
                case 7: shv = s3 * x * z; break;
                default: shv = 0.5f * s3 * (x * x - y * y); break;
            }
            g_shg[(size_t)e * 9 + f] = shv;
        }
    }

    int i = nidx[2 * e], j = nidx[2 * e + 1];
    const float* __restrict__ Zi = g_z + (size_t)i * (NM * NF) + f;
    const float* __restrict__ Zj = g_z + (size_t)j * (NM * NF) + f;
    float v[NM];
    float n2 = 0.f;
    float bf = b1[f];
#pragma unroll
    for (int m = 0; m < NM; ++m) {
        float val = Zi[(size_t)m * NF] + Zj[(size_t)m * NF];
        if (m == 0) val += bf;
        v[m] = val;
        n2 += val * val;
    }
    float sc = rsqrtf(n2 + 1e-6f);
    float s = v[0] * sc;
    float sp = fmaxf(s, 0.f) + log1pf(expf(-fabsf(s)));
    float t = tanhf(sp);
    float sig = 1.f / (1.f + expf(-s));
    float dm = t + s * (1.f - t * t) * sig;
    size_t base = (size_t)e * (NM * NF) + f;
    g_y1[base] = s * t;
#pragma unroll
    for (int m = 1; m < NM; ++m) g_y1[base + (size_t)m * NF] = v[m] * sc * dm;
}

// ---------------- tensor product (scalar) ----------------
template <int P, int L1, int L2, int L3, int MO>
__device__ __forceinline__ void tp_path(const float* __restrict__ wtp, int f,
                                        const float* __restrict__ Ms,
                                        const float (&vv)[3], const float (&yreg)[25],
                                        float (&acc)[25]) {
    float scale = wtp[P * NF + f] * vv[L1];
#pragma unroll
    for (int c = 0; c < 2 * L3 + 1; ++c) {
        float s = 0.f;
#pragma unroll
        for (int b = 0; b < 2 * L2 + 1; ++b)
            s += Ms[MO + b * (2 * L3 + 1) + c] * yreg[L2 * L2 + b];
        acc[L3 * L3 + c] += scale * s;
    }
}

__global__ __launch_bounds__(128) void tp_kernel(const float* __restrict__ wtp,
                                                 float* __restrict__ Out) {
    int e = blockIdx.x, f = threadIdx.x;
    __shared__ float Ms[703];
    __shared__ float shs[9];
    if (f < 9) shs[f] = g_shg[(size_t)e * 9 + f];
    __syncthreads();

    for (int idx = f; idx < 703; idx += 128) {
        int p = 0;
        while (dMOFF[p + 1] <= idx) ++p;
        int l1 = dPL1[p], l3 = dPL3[p];
        int local = idx - dMOFF[p];
        int n3 = 2 * l3 + 1;
        int b = local / n3, c = local - b * n3;
        const float* Cp = g_C + p * 729 + b * 9 + c;
        float s = 0.f;
        for (int a = 0; a <= 2 * l1; ++a) s += Cp[a * 81] * shs[l1 * l1 + a];
        Ms[idx] = s;
    }
    __syncthreads();

    float yreg[25];
    size_t base = (size_t)e * (NM * NF) + f;
#pragma unroll
    for (int m = 0; m < NM; ++m) yreg[m] = g_y0[base + (size_t)m * NF];
    float vv[3];
#pragma unroll
    for (int l = 0; l < 3; ++l) vv[l] = g_v[((size_t)e * 3 + l) * NF + f];
    float acc[25];
#pragma unroll
    for (int m = 0; m < NM; ++m) acc[m] = 0.f;

    tp_path<0, 0, 0, 0, 0>(wtp, f, Ms, vv, yreg, acc);
    tp_path<1, 0, 1, 1, 1>(wtp, f, Ms, vv, yreg, acc);
    tp_path<2, 0, 2, 2, 10>(wtp, f, Ms, vv, yreg, acc);
    tp_path<3, 0, 3, 3, 35>(wtp, f, Ms, vv, yreg, acc);
    tp_path<4, 0, 4, 4, 84>(wtp, f, Ms, vv, yreg, acc);
    tp_path<5, 1, 0, 1, 165>(wtp, f, Ms, vv, yreg, acc);
    tp_path<6, 1, 1, 0, 168>(wtp, f, Ms, vv, yreg, acc);
    tp_path<7, 1, 1, 2, 171>(wtp, f, Ms, vv, yreg, acc);
    tp_path<8, 1, 2, 1, 186>(wtp, f, Ms, vv, yreg, acc);
    tp_path<9, 1, 2, 3, 201>(wtp, f, Ms, vv, yreg, acc);
    tp_path<10, 1, 3, 2, 236>(wtp, f, Ms, vv, yreg, acc);
    tp_path<11, 1, 3, 4, 271>(wtp, f, Ms, vv, yreg, acc);
    tp_path<12, 1, 4, 3, 334>(wtp, f, Ms, vv, yreg, acc);
    tp_path<13, 2, 0, 2, 397>(wtp, f, Ms, vv, yreg, acc);
    tp_path<14, 2, 1, 1, 402>(wtp, f, Ms, vv, yreg, acc);
    tp_path<15, 2, 1, 3, 411>(wtp, f, Ms, vv, yreg, acc);
    tp_path<16, 2, 2, 0, 432>(wtp, f, Ms, vv, yreg, acc);
    tp_path<17, 2, 2, 2, 437>(wtp, f, Ms, vv, yreg, acc);
    tp_path<18, 2, 2, 4, 462>(wtp, f, Ms, vv, yreg, acc);
    tp_path<19, 2, 3, 1, 507>(wtp, f, Ms, vv, yreg, acc);
    tp_path<20, 2, 3, 3, 528>(wtp, f, Ms, vv, yreg, acc);
    tp_path<21, 2, 4, 2, 577>(wtp, f, Ms, vv, yreg, acc);
    tp_path<22, 2, 4, 4, 622>(wtp, f, Ms, vv, yreg, acc);

#pragma unroll
    for (int m = 0; m < NM; ++m) Out[base + (size_t)m * NF] = acc[m];
}

// ---------------- launch ----------------
extern "C" void kernel_launch(void* const* d_in, const int* in_sizes, int n_in,
                              void* d_out, int out_size) {
    const float* desc = (const float*)d_in[0];
    const int*   nidx = (const int*)d_in[1];
    const float* disp = (const float*)d_in[2];
    const float* W1   = (const float*)d_in[3];
    const float* b1   = (const float*)d_in[4];
    const float* W2   = (const float*)d_in[5];
    const float* b2   = (const float*)d_in[6];
    const float* W3   = (const float*)d_in[7];
    const float* b3   = (const float*)d_in[8];
    const float* wtp  = (const float*)d_in[9];
    float* out = (float*)d_out;
    (void)in_sizes; (void)n_in; (void)out_size;

    static int attr_set = 0;
    if (!attr_set) {
        cudaFuncSetAttribute(tc_gemm_atom, cudaFuncAttributeMaxDynamicSharedMemorySize, TC_SMEM_BYTES);
        cudaFuncSetAttribute(tc_gemm_edge, cudaFuncAttributeMaxDynamicSharedMemorySize, TC_SMEM_BYTES);
        cudaFuncSetAttribute(wfrag_init, cudaFuncAttributeMaxDynamicSharedMemorySize, WF_SMEM_BYTES);
        attr_set = 1;
    }

    // order: wfrag(1), gemm_atom(2), nmg(3), gemm_edge(4) <- profiled, cg_init(5), tp(6)
    wfrag_init<<<13, 256, WF_SMEM_BYTES>>>(W1, W2, W3);
    tc_gemm_atom<<<dim3(N_A / 128, NM), 512, TC_SMEM_BYTES>>>(desc);
    norm_mish_gather<<<N_E, 128>>>(nidx, b1, disp);
    tc_gemm_edge<<<dim3(N_E / 128, NM + 3), 512, TC_SMEM_BYTES>>>(b2, b3);
    cg_init_kernel<<<dim3(23, 8), 128>>>();
    tp_kernel<<<N_E, 128>>>(wtp, out);
}

// round 17
// speedup vs baseline: 1.4624x; 1.1078x over previous
#include <cuda_runtime.h>
#include <cuda_fp16.h>
#include <math.h>
#include <stdint.h>

#define N_E 16384
#define N_A 4096
#define NF  128
#define NM  25

// ---------------- scratch (device globals; no allocation allowed) ----------------
__device__ float g_y0[(size_t)N_E * NM * NF];   // final y (post gemm2+res)
__device__ float g_y1[(size_t)N_E * NM * NF];   // post-mish edge features
__device__ float g_z[(size_t)N_A * NM * NF];    // per-ATOM W1 transform
__device__ float g_rad[(size_t)N_E * NF];
__device__ float g_shg[(size_t)N_E * 9];
__device__ float g_v[(size_t)N_E * 3 * NF];
__device__ float g_Ct[23 * 81 * 8];             // CG transposed: [p][b][c][a] (a contiguous, padded 8)
__device__ int   g_LUT[703];                    // packed (p<<16)|(b<<8)|c per Ms index
// precomputed B register fragments (fp16): [13 mats][2 wc64][8 kstep][4 bt][32 lane]
__device__ uint4 g_Bf[13 * 2 * 8 * 4 * 32];

__constant__ int dPL1[23]  = {0,0,0,0,0, 1,1,1,1,1,1,1,1, 2,2,2,2,2,2,2,2,2,2};
__constant__ int dPL2[23]  = {0,1,2,3,4, 0,1,1,2,2,3,3,4, 0,1,1,2,2,2,3,3,4,4};
__constant__ int dPL3[23]  = {0,1,2,3,4, 1,0,2,1,3,2,4,3, 2,1,3,0,2,4,1,3,2,4};
__constant__ int dMOFF[24] = {0,1,10,35,84,165,168,171,186,201,236,271,334,
                              397,402,411,432,437,462,507,528,577,622,703};

// ---------------- CG table computation (double, matches reference) ----------------
__device__ double factd(int n) { double r = 1.0; for (int i = 2; i <= n; ++i) r *= (double)i; return r; }

__device__ double cgc(int l1, int l2, int l3, int m1, int m2, int m3) {
    if (m1 + m2 != m3) return 0.0;
    if (l3 < abs(l1 - l2) || l3 > l1 + l2) return 0.0;
    double pre = sqrt((double)(2 * l3 + 1) * factd(l3 + l1 - l2) * factd(l3 - l1 + l2) *
                      factd(l1 + l2 - l3) / factd(l1 + l2 + l3 + 1));
    pre *= sqrt(factd(l3 + m3) * factd(l3 - m3) * factd(l1 - m1) * factd(l1 + m1) *
                factd(l2 - m2) * factd(l2 + m2));
    double s = 0.0;
    for (int k = 0; k <= l1 + l2 - l3; ++k) {
        int a0 = k, a1 = l1 + l2 - l3 - k, a2 = l1 - m1 - k, a3 = l2 + m2 - k;
        int a4 = l3 - l2 + m1 + k, a5 = l3 - l1 - m2 + k;
        if (a0 < 0 || a1 < 0 || a2 < 0 || a3 < 0 || a4 < 0 || a5 < 0) continue;
        double d = factd(a0) * factd(a1) * factd(a2) * factd(a3) * factd(a4) * factd(a5);
        s += ((k & 1) ? -1.0 : 1.0) / d;
    }
    return pre * s;
}

__device__ void u_elem(int l, int a, int A, double& re, double& im) {
    re = 0.0; im = 0.0;
    const double is2 = 0.70710678118654752440;
    int mA = A - l, ma = a - l;
    if (mA == 0) { if (ma == 0) re = 1.0; return; }
    int m = mA > 0 ? mA : -mA;
    double sgn = (m & 1) ? -1.0 : 1.0;
    if (mA > 0) {
        if (ma == m)       re = sgn * is2;
        else if (ma == -m) re = is2;
    } else {
        if (ma == m)       im = sgn * is2;
        else if (ma == -m) im = -is2;
    }
}

// grid (23, 8): computes g_Ct; block (0,0) also fills g_LUT
__global__ void cg_init_kernel() {
    int p = blockIdx.x;
    int l1 = dPL1[p], l2 = dPL2[p], l3 = dPL3[p];
    int n1 = 2 * l1 + 1, n2 = 2 * l2 + 1, n3 = 2 * l3 + 1;
    int total = n1 * n2 * n3;
    int start = blockIdx.y * blockDim.x + threadIdx.x;
    int stride = blockDim.x * gridDim.y;
    for (int idx = start; idx < total; idx += stride) {
        int A  = idx / (n2 * n3);
        int rm = idx % (n2 * n3);
        int B  = rm / n3;
        int Cc = rm % n3;
        double acc = 0.0;
        for (int a = 0; a < n1; ++a) {
            double u1r, u1i; u_elem(l1, a, A, u1r, u1i);
            if (u1r == 0.0 && u1i == 0.0) continue;
            int m1 = a - l1;
            for (int b = 0; b < n2; ++b) {
                double u2r, u2i; u_elem(l2, b, B, u2r, u2i);
                if (u2r == 0.0 && u2i == 0.0) continue;
                int m2 = b - l2;
                int m3 = m1 + m2;
                if (m3 < -l3 || m3 > l3) continue;
                double cg = cgc(l1, l2, l3, m1, m2, m3);
                if (cg == 0.0) continue;
                int c = l3 + m3;
                double u3r, u3i; u_elem(l3, c, Cc, u3r, u3i);
                double pr = u1r * u2r - u1i * u2i;
                double pi = u1r * u2i + u1i * u2r;
                acc += cg * (pr * u3r + pi * u3i);
            }
        }
        // transposed layout: a contiguous (A is the l1-index here)
        g_Ct[(p * 81 + B * 9 + Cc) * 8 + A] = (float)acc;
    }
    // block (0,0): fill LUT (p,b,c per Ms index)
    if (p == 0 && blockIdx.y == 0) {
        for (int idx = threadIdx.x; idx < 703; idx += blockDim.x) {
            int q = 0;
            while (dMOFF[q + 1] <= idx) ++q;
            int l3q = dPL3[q];
            int n3q = 2 * l3q + 1;
            int local = idx - dMOFF[q];
            int b = local / n3q, c = local - b * n3q;
            g_LUT[idx] = (q << 16) | (b << 8) | c;
        }
    }
}

// ================= mma.sync helpers =================
__device__ __forceinline__ uint32_t smem_u32(const void* p) {
    uint32_t a;
    asm("{ .reg .u64 t; cvta.to.shared.u64 t, %1; cvt.u32.u64 %0, t; }" : "=r"(a) : "l"(p));
    return a;
}
__device__ __forceinline__ void ldm4(uint32_t addr, uint32_t& a0, uint32_t& a1,
                                     uint32_t& a2, uint32_t& a3) {
    asm volatile("ldmatrix.sync.aligned.m8n8.x4.shared.b16 {%0,%1,%2,%3}, [%4];"
                 : "=r"(a0), "=r"(a1), "=r"(a2), "=r"(a3) : "r"(addr));
}
__device__ __forceinline__ void mma16816(float* c,
                                         uint32_t a0, uint32_t a1, uint32_t a2, uint32_t a3,
                                         uint32_t b0, uint32_t b1) {
    asm volatile("mma.sync.aligned.m16n8k16.row.col.f32.f16.f16.f32 "
                 "{%0,%1,%2,%3}, {%4,%5,%6,%7}, {%8,%9}, {%0,%1,%2,%3};"
                 : "+f"(c[0]), "+f"(c[1]), "+f"(c[2]), "+f"(c[3])
                 : "r"(a0), "r"(a1), "r"(a2), "r"(a3), "r"(b0), "r"(b1));
}

// padded row-major f16 tile: 128 rows x 128 cols, row stride 272 bytes (136 halves)
#define ROWB 272
#define TILE_B (128 * ROWB)           // 34816 bytes per tile
#define TC_SMEM_BYTES (2 * TILE_B)    // A_hi, A_lo = 69632
#define WF_SMEM_BYTES TILE_B

// ---------------- precompute B fragments (per weight matrix, fp16) ----------------
__global__ __launch_bounds__(256) void wfrag_init(const float* __restrict__ W1,
                                                  const float* __restrict__ W2,
                                                  const float* __restrict__ W3) {
    extern __shared__ char smem[];
    char* sH = smem;
    const int mat = blockIdx.x;
    const float* __restrict__ W = (mat < 5) ? (W1 + (size_t)mat * NF * NF)
                               : (mat < 10) ? (W2 + (size_t)(mat - 5) * NF * NF)
                                            : (W3 + (size_t)(mat - 10) * NF * NF);
    const int tid = threadIdx.x;

#pragma unroll
    for (int t = 0; t < 16; ++t) {
        int pos = t * 256 + tid;                // 4096 float4 slots
        int k = pos >> 5, n0 = (pos & 31) * 4;
        float4 w = *reinterpret_cast<const float4*>(W + (size_t)k * NF + n0);
        float wv[4] = {w.x, w.y, w.z, w.w};
#pragma unroll
        for (int q = 0; q < 4; ++q) {
            __half h = __float2half_rn(wv[q]);
            uint32_t off = (uint32_t)(n0 + q) * ROWB + (uint32_t)k * 2;
            *reinterpret_cast<unsigned short*>(sH + off) = reinterpret_cast<unsigned short&>(h);
        }
    }
    __syncthreads();

    if (tid < 64) {
        const int wc = tid >> 5, lane = tid & 31;
        const int b_n = ((lane >> 4) & 1) * 8 + (lane & 7);
        const int b_k = ((lane >> 3) & 1) * 8;
        const uint32_t baseH = smem_u32(sH);
        for (int kk = 0; kk < 8; ++kk) {
            for (int bt = 0; bt < 4; ++bt) {
                uint32_t boff = (uint32_t)(wc * 64 + bt * 16 + b_n) * ROWB +
                                (uint32_t)(kk * 16 + b_k) * 2;
                uint4 h;
                ldm4(baseH + boff, h.x, h.y, h.z, h.w);
                int idx = (((mat * 2 + wc) * 8 + kk) * 4 + bt) * 32 + lane;
                g_Bf[idx] = h;
            }
        }
    }
}

// ================= GEMM core: 16 warps = 8 rowgroups x 2 colgroups, warp tile 16x64 =================
struct GemmIO {
    const float* X;
    size_t x_row_stride;
    float* Y;
    size_t y_row_stride;
    const float* bias;
    bool residual;
    const float* res;
    int mat;
};

__device__ __forceinline__ void gemm_core(const GemmIO io, int e0) {
    extern __shared__ char smem[];
    char* sA_hi = smem;
    char* sA_lo = smem + TILE_B;

    const int tid = threadIdx.x;
    const int wid = tid >> 5;
    const int lid = tid & 31;

    // ---- stage X into A_hi/A_lo (fp16 split; x = xh + xl to ~2^-22) ----
#pragma unroll
    for (int t = 0; t < 8; ++t) {
        int pos = t * 512 + tid;
        int r = pos >> 5, k0 = (pos & 31) * 4;
        float4 x = *reinterpret_cast<const float4*>(io.X + (size_t)(e0 + r) * io.x_row_stride + k0);
        __half2 h01 = __floats2half2_rn(x.x, x.y);
        __half2 h23 = __floats2half2_rn(x.z, x.w);
        __half2 l01 = __floats2half2_rn(x.x - __low2float(h01), x.y - __high2float(h01));
        __half2 l23 = __floats2half2_rn(x.z - __low2float(h23), x.w - __high2float(h23));
        uint32_t off = (uint32_t)r * ROWB + (uint32_t)k0 * 2;
        *reinterpret_cast<uint32_t*>(sA_hi + off)     = reinterpret_cast<uint32_t&>(h01);
        *reinterpret_cast<uint32_t*>(sA_hi + off + 4) = reinterpret_cast<uint32_t&>(h23);
        *reinterpret_cast<uint32_t*>(sA_lo + off)     = reinterpret_cast<uint32_t&>(l01);
        *reinterpret_cast<uint32_t*>(sA_lo + off + 4) = reinterpret_cast<uint32_t&>(l23);
    }
    __syncthreads();

    // ---- mainloop: warp tile 16 rows x 64 cols ----
    const int wr = wid >> 1;            // 0..7 (row group of 16)
    const int wc = wid & 1;             // 0..1 (col group of 64)
    const int r0 = wr * 16;

    const uint32_t aBaseHi = smem_u32(sA_hi);
    const uint32_t aBaseLo = smem_u32(sA_lo);
    const int a_r = lid & 15;
    const int a_k = (lid >> 4) * 8;

    const uint4* __restrict__ Bf = g_Bf + ((size_t)(io.mat * 2 + wc) * 8) * 128 + lid;

    float acc[8][4];
#pragma unroll
    for (int t = 0; t < 8; ++t)
#pragma unroll
        for (int q = 0; q < 4; ++q) acc[t][q] = 0.f;

    uint32_t ah[2][4], al[2][4];
    uint4 bh[2][4];

    {
        uint32_t aoff = (uint32_t)(r0 + a_r) * ROWB + (uint32_t)(a_k) * 2;
        ldm4(aBaseHi + aoff, ah[0][0], ah[0][1], ah[0][2], ah[0][3]);
        ldm4(aBaseLo + aoff, al[0][0], al[0][1], al[0][2], al[0][3]);
    }
#pragma unroll
    for (int bt = 0; bt < 4; ++bt) bh[0][bt] = Bf[bt * 32];

#pragma unroll
    for (int kk = 0; kk < 8; ++kk) {
        const int cur = kk & 1;
        const int nxt = cur ^ 1;
        if (kk < 7) {
#pragma unroll
            for (int bt = 0; bt < 4; ++bt) bh[nxt][bt] = Bf[(kk + 1) * 128 + bt * 32];
            uint32_t aoff = (uint32_t)(r0 + a_r) * ROWB + (uint32_t)((kk + 1) * 16 + a_k) * 2;
            ldm4(aBaseHi + aoff, ah[nxt][0], ah[nxt][1], ah[nxt][2], ah[nxt][3]);
            ldm4(aBaseLo + aoff, al[nxt][0], al[nxt][1], al[nxt][2], al[nxt][3]);
        }
#pragma unroll
        for (int bt = 0; bt < 4; ++bt) {
            float* c0p = acc[bt * 2];
            float* c1p = acc[bt * 2 + 1];
            mma16816(c0p, ah[cur][0], ah[cur][1], ah[cur][2], ah[cur][3],
                     bh[cur][bt].x, bh[cur][bt].y);
            mma16816(c1p, ah[cur][0], ah[cur][1], ah[cur][2], ah[cur][3],
                     bh[cur][bt].z, bh[cur][bt].w);
            mma16816(c0p, al[cur][0], al[cur][1], al[cur][2], al[cur][3],
                     bh[cur][bt].x, bh[cur][bt].y);
            mma16816(c1p, al[cur][0], al[cur][1], al[cur][2], al[cur][3],
                     bh[cur][bt].z, bh[cur][bt].w);
        }
    }

    // ---- direct fragment epilogue ----
    const int c0w = wc * 64;
    const int fr = lid >> 2;
    const int fc = (lid & 3) * 2;
#pragma unroll
    for (int nt = 0; nt < 8; ++nt) {
        float* a = acc[nt];
        int rr = r0 + fr;
        int cc = c0w + nt * 8 + fc;
        float2 v0 = make_float2(a[0], a[1]);
        float2 v1 = make_float2(a[2], a[3]);
        if (io.bias) {
            float bx = io.bias[cc], by = io.bias[cc + 1];
            v0.x += bx; v0.y += by;
            v1.x += bx; v1.y += by;
        }
        size_t o0 = (size_t)(e0 + rr) * io.y_row_stride + cc;
        size_t o1 = (size_t)(e0 + rr + 8) * io.y_row_stride + cc;
        if (io.residual) {
            float2 q0 = *reinterpret_cast<const float2*>(io.res + o0);
            float2 q1 = *reinterpret_cast<const float2*>(io.res + o1);
            v0.x += q0.x; v0.y += q0.y;
            v1.x += q1.x; v1.y += q1.y;
        }
        *reinterpret_cast<float2*>(io.Y + o0) = v0;
        *reinterpret_cast<float2*>(io.Y + o1) = v1;
    }
}

// atoms: X = desc, Y = g_z, no bias
__global__ __launch_bounds__(512, 1) void tc_gemm_atom(const float* __restrict__ desc) {
    const int m = blockIdx.y;
    const int l = (m >= 16) ? 4 : (m >= 9) ? 3 : (m >= 4) ? 2 : (m >= 1) ? 1 : 0;
    GemmIO io;
    io.X = desc + (size_t)m * NF;  io.x_row_stride = NM * NF;
    io.Y = g_z + (size_t)m * NF;   io.y_row_stride = NM * NF;
    io.bias = nullptr; io.residual = false; io.res = nullptr;
    io.mat = l;
    gemm_core(io, blockIdx.x * 128);
}

// merged edge GEMM: m in [0,25) = W2 (+residual, b2 @ m==0); m in [25,28) = W3 (b3 @ m==25)
__global__ __launch_bounds__(512, 1) void tc_gemm_edge(const float* __restrict__ b2,
                                                       const float* __restrict__ b3) {
    const int m = blockIdx.y;
    GemmIO io;
    if (m < NM) {
        const int l = (m >= 16) ? 4 : (m >= 9) ? 3 : (m >= 4) ? 2 : (m >= 1) ? 1 : 0;
        io.X = g_y1 + (size_t)m * NF;  io.x_row_stride = NM * NF;
        io.Y = g_y0 + (size_t)m * NF;  io.y_row_stride = NM * NF;
        io.bias = (m == 0) ? b2 : nullptr;
        io.residual = true; io.res = g_y1 + (size_t)m * NF;
        io.mat = 5 + l;
    } else {
        const int l = m - NM;
        io.X = g_rad;                  io.x_row_stride = NF;
        io.Y = g_v + (size_t)l * NF;   io.y_row_stride = 3 * NF;
        io.bias = (l == 0) ? b3 : nullptr;
        io.residual = false; io.res = nullptr;
        io.mat = 10 + l;
    }
    gemm_core(io, blockIdx.x * 128);
}

// ---------------- fused gather + b1 + normalize + mish + rad/sh ----------------
__global__ __launch_bounds__(128) void norm_mish_gather(const int* __restrict__ nidx,
                                                        const float* __restrict__ b1,
                                                        const float* __restrict__ disp) {
    int e = blockIdx.x, f = threadIdx.x;

    {
        float dx = disp[3 * e], dy = disp[3 * e + 1], dz = disp[3 * e + 2];
        float r = sqrtf(dx * dx + dy * dy + dz * dz + 1e-12f);
        float x = dx / r, y = dy / r, z = dz / r;
        float uc = r / 5.0f;
        float denom = fmaxf(1.f - uc * uc, 1e-9f);
        float cut = (uc < 1.f) ? expf(1.f - 1.f / denom) : 0.f;
        float ang = 3.14159265358979323846f * r / 5.0f;
        g_rad[(size_t)e * NF + f] = cosf((float)f * ang) * cut;
        if (f < 9) {
            const float s3 = 1.7320508075688772f;
            float shv;
            switch (f) {
                case 0: shv = 1.f; break;
                case 1: shv = y; break;
                case 2: shv = z; break;
                case 3: shv = x; break;
                case 4: shv = s3 * x * y; break;
                case 5: shv = s3 * y * z; break;
                case 6: shv = 0.5f * (3.f * z * z - 1.f); break;
                case 7: shv = s3 * x * z; break;
                default: shv = 0.5f * s3 * (x * x - y * y); break;
            }
            g_shg[(size_t)e * 9 + f] = shv;
        }
    }

    int i = nidx[2 * e], j = nidx[2 * e + 1];
    const float* __restrict__ Zi = g_z + (size_t)i * (NM * NF) + f;
    const float* __restrict__ Zj = g_z + (size_t)j * (NM * NF) + f;
    float v[NM];
    float n2 = 0.f;
    float bf = b1[f];
#pragma unroll
    for (int m = 0; m < NM; ++m) {
        float val = Zi[(size_t)m * NF] + Zj[(size_t)m * NF];
        if (m == 0) val += bf;
        v[m] = val;
        n2 += val * val;
    }
    float sc = rsqrtf(n2 + 1e-6f);
    float s = v[0] * sc;
    float sp = fmaxf(s, 0.f) + log1pf(expf(-fabsf(s)));
    float t = tanhf(sp);
    float sig = 1.f / (1.f + expf(-s));
    float dm = t + s * (1.f - t * t) * sig;
    size_t base = (size_t)e * (NM * NF) + f;
    g_y1[base] = s * t;
#pragma unroll
    for (int m = 1; m < NM; ++m) g_y1[base + (size_t)m * NF] = v[m] * sc * dm;
}

// ---------------- tensor product (scalar; LUT-based Ms build) ----------------
template <int P, int L1, int L2, int L3, int MO>
__device__ __forceinline__ void tp_path(const float* __restrict__ wtp, int f,
                                        const float* __restrict__ Ms,
                                        const float (&vv)[3], const float (&yreg)[25],
                                        float (&acc)[25]) {
    float scale = wtp[P * NF + f] * vv[L1];
#pragma unroll
    for (int c = 0; c < 2 * L3 + 1; ++c) {
        float s = 0.f;
#pragma unroll
        for (int b = 0; b < 2 * L2 + 1; ++b)
            s += Ms[MO + b * (2 * L3 + 1) + c] * yreg[L2 * L2 + b];
        acc[L3 * L3 + c] += scale * s;
    }
}

__global__ __launch_bounds__(128) void tp_kernel(const float* __restrict__ wtp,
                                                 float* __restrict__ Out) {
    int e = blockIdx.x, f = threadIdx.x;
    __shared__ float Ms[703];
    __shared__ float shs[9];
    if (f < 9) shs[f] = g_shg[(size_t)e * 9 + f];
    __syncthreads();

    // LUT-based contracted-M build: M[idx] = sum_a Ct[p][b][c][a] * shs[l1^2+a]
    for (int idx = f; idx < 703; idx += 128) {
        int u = g_LUT[idx];
        int p = u >> 16, b = (u >> 8) & 255, c = u & 255;
        int l1 = dPL1[p];
        const float* base = g_Ct + ((p * 81 + b * 9 + c) << 3);
        float s = 0.f;
        for (int a = 0; a <= 2 * l1; ++a) s += base[a] * shs[l1 * l1 + a];
        Ms[idx] = s;
    }
    __syncthreads();

    float yreg[25];
    size_t base = (size_t)e * (NM * NF) + f;
#pragma unroll
    for (int m = 0; m < NM; ++m) yreg[m] = g_y0[base + (size_t)m * NF];
    float vv[3];
#pragma unroll
    for (int l = 0; l < 3; ++l) vv[l] = g_v[((size_t)e * 3 + l) * NF + f];
    float acc[25];
#pragma unroll
    for (int m = 0; m < NM; ++m) acc[m] = 0.f;

    tp_path<0, 0, 0, 0, 0>(wtp, f, Ms, vv, yreg, acc);
    tp_path<1, 0, 1, 1, 1>(wtp, f, Ms, vv, yreg, acc);
    tp_path<2, 0, 2, 2, 10>(wtp, f, Ms, vv, yreg, acc);
    tp_path<3, 0, 3, 3, 35>(wtp, f, Ms, vv, yreg, acc);
    tp_path<4, 0, 4, 4, 84>(wtp, f, Ms, vv, yreg, acc);
    tp_path<5, 1, 0, 1, 165>(wtp, f, Ms, vv, yreg, acc);
    tp_path<6, 1, 1, 0, 168>(wtp, f, Ms, vv, yreg, acc);
    tp_path<7, 1, 1, 2, 171>(wtp, f, Ms, vv, yreg, acc);
    tp_path<8, 1, 2, 1, 186>(wtp, f, Ms, vv, yreg, acc);
    tp_path<9, 1, 2, 3, 201>(wtp, f, Ms, vv, yreg, acc);
    tp_path<10, 1, 3, 2, 236>(wtp, f, Ms, vv, yreg, acc);
    tp_path<11, 1, 3, 4, 271>(wtp, f, Ms, vv, yreg, acc);
    tp_path<12, 1, 4, 3, 334>(wtp, f, Ms, vv, yreg, acc);
    tp_path<13, 2, 0, 2, 397>(wtp, f, Ms, vv, yreg, acc);
    tp_path<14, 2, 1, 1, 402>(wtp, f, Ms, vv, yreg, acc);
    tp_path<15, 2, 1, 3, 411>(wtp, f, Ms, vv, yreg, acc);
    tp_path<16, 2, 2, 0, 432>(wtp, f, Ms, vv, yreg, acc);
    tp_path<17, 2, 2, 2, 437>(wtp, f, Ms, vv, yreg, acc);
    tp_path<18, 2, 2, 4, 462>(wtp, f, Ms, vv, yreg, acc);
    tp_path<19, 2, 3, 1, 507>(wtp, f, Ms, vv, yreg, acc);
    tp_path<20, 2, 3, 3, 528>(wtp, f, Ms, vv, yreg, acc);
    tp_path<21, 2, 4, 2, 577>(wtp, f, Ms, vv, yreg, acc);
    tp_path<22, 2, 4, 4, 622>(wtp, f, Ms, vv, yreg, acc);

#pragma unroll
    for (int m = 0; m < NM; ++m) Out[base + (size_t)m * NF] = acc[m];
}

// ---------------- launch ----------------
extern "C" void kernel_launch(void* const* d_in, const int* in_sizes, int n_in,
                              void* d_out, int out_size) {
    const float* desc = (const float*)d_in[0];
    const int*   nidx = (const int*)d_in[1];
    const float* disp = (const float*)d_in[2];
    const float* W1   = (const float*)d_in[3];
    const float* b1   = (const float*)d_in[4];
    const float* W2   = (const float*)d_in[5];
    const float* b2   = (const float*)d_in[6];
    const float* W3   = (const float*)d_in[7];
    const float* b3   = (const float*)d_in[8];
    const float* wtp  = (const float*)d_in[9];
    float* out = (float*)d_out;
    (void)in_sizes; (void)n_in; (void)out_size;

    static int attr_set = 0;
    if (!attr_set) {
        cudaFuncSetAttribute(tc_gemm_atom, cudaFuncAttributeMaxDynamicSharedMemorySize, TC_SMEM_BYTES);
        cudaFuncSetAttribute(tc_gemm_edge, cudaFuncAttributeMaxDynamicSharedMemorySize, TC_SMEM_BYTES);
        cudaFuncSetAttribute(wfrag_init, cudaFuncAttributeMaxDynamicSharedMemorySize, WF_SMEM_BYTES);
        attr_set = 1;
    }

    // order: wfrag(1), gemm_atom(2), nmg(3), gemm_edge(4) <- profiled, cg_init(5), tp(6)
    wfrag_init<<<13, 256, WF_SMEM_BYTES>>>(W1, W2, W3);
    tc_gemm_atom<<<dim3(N_A / 128, NM), 512, TC_SMEM_BYTES>>>(desc);
    norm_mish_gather<<<N_E, 128>>>(nidx, b1, disp);
    tc_gemm_edge<<<dim3(N_E / 128, NM + 3), 512, TC_SMEM_BYTES>>>(b2, b3);
    cg_init_kernel<<<dim3(23, 8), 128>>>();
    tp_kernel<<<N_E, 128>>>(wtp, out);
}